// round 8
// baseline (speedup 1.0000x reference)
#include <cuda_runtime.h>
#include <cuda_bf16.h>
#include <cstdint>
#include <cstddef>

#define HID 1024
#define NB 128
#define TSTEPS 256
#define HORIZON 24
#define NCTA 128
#define NTHR 256
#define HP 512                 // bf16x2 (hi,lo) pairs per 1024-wide row
#define XP 16                  // pairs in x/pred block (32 k, zero padded)
#define P0 (XP + HP)           // 528 pairs  : enc0/dec0 K
#define P1 (2 * HP)            // 1024 pairs : enc1/dec1 K

// ---------------- persistent scratch (__device__ globals; no allocs) -------------
// weights: [interleaved_col (4j+g)][pair] as uint2(hi bf16x2, lo bf16x2)
__device__ __align__(16) uint2 g_We0[(size_t)4096 * P0];
__device__ __align__(16) uint2 g_We1[(size_t)4096 * P1];
__device__ __align__(16) uint2 g_Wd0[(size_t)4096 * P0];
__device__ __align__(16) uint2 g_Wd1[(size_t)4096 * P1];
// activations as split pairs
__device__ __align__(16) uint2 g_ys0p[(size_t)TSTEPS * NB * HP];
__device__ __align__(16) uint2 g_hBp[2 * NB * HP];
__device__ __align__(16) uint2 g_hd0p[2 * NB * HP];
__device__ __align__(16) uint2 g_hd1p[2 * NB * HP];
__device__ __align__(16) uint2 g_zerop[NB * HP];
__device__ __align__(16) uint2 g_xp[(size_t)TSTEPS * NB * XP];
__device__ __align__(16) uint2 g_predp[NB * XP];
__device__ float g_c0[NB * HID];
__device__ float g_c1[NB * HID];
__device__ unsigned g_bar_cnt;
__device__ volatile unsigned g_bar_epoch;

// ---------------- helpers --------------------------------------------------------
__device__ __forceinline__ uint32_t bf2pack(float hi, float lo) {
  uint32_t r;
  asm("cvt.rn.bf16x2.f32 %0, %1, %2;" : "=r"(r) : "f"(hi), "f"(lo));
  return r;
}
__device__ __forceinline__ uint2 split2(float v0, float v1) {
  uint32_t hp = bf2pack(v1, v0);
  float h0 = __uint_as_float(hp << 16);
  float h1 = __uint_as_float(hp & 0xFFFF0000u);
  uint32_t lp = bf2pack(v1 - h1, v0 - h0);
  return make_uint2(hp, lp);
}
__device__ __forceinline__ void mma_bf16(float d[4], const uint32_t a[4], const uint32_t b[2]) {
  asm volatile(
      "mma.sync.aligned.m16n8k16.row.col.f32.bf16.bf16.f32 "
      "{%0,%1,%2,%3}, {%4,%5,%6,%7}, {%8,%9}, {%0,%1,%2,%3};\n"
      : "+f"(d[0]), "+f"(d[1]), "+f"(d[2]), "+f"(d[3])
      : "r"(a[0]), "r"(a[1]), "r"(a[2]), "r"(a[3]), "r"(b[0]), "r"(b[1]));
}
__device__ __forceinline__ float sigmoidf_(float x) { return 1.f / (1.f + expf(-x)); }

__device__ __forceinline__ uint32_t smem_u32(const void* p) {
  uint32_t a;
  asm("{ .reg .u64 t; cvta.to.shared.u64 t, %1; cvt.u32.u64 %0, t; }" : "=r"(a) : "l"(p));
  return a;
}
#define CP_ASYNC16(dst, src) \
  asm volatile("cp.async.cg.shared.global [%0], [%1], 16;" :: "r"(dst), "l"(src) : "memory")
#define CP_COMMIT() asm volatile("cp.async.commit_group;" ::: "memory")
#define CP_WAIT1()  asm volatile("cp.async.wait_group 1;" ::: "memory")
#define CP_WAIT0()  asm volatile("cp.async.wait_group 0;" ::: "memory")

// ---------------- persistent wavefront kernel ------------------------------------
// 128 CTAs, 2 groups of 64. Group-CTA n owns full M=128 x cols [n*64, n*64+64).
// 8 warps: wm = wid>>1 (M quarter), wk = wid&1 (K-split half of each super).
// Super = 2 chunks of K=16 (8 pairs). smem: 4 chunk slots (2 stages x 2), XOR
// swizzle f(r) = (r&2)*3 -> conflict-free frag LDS.64 and 16B staging stores.
__global__ void __launch_bounds__(NTHR, 1) lstm_persist(
    const float* __restrict__ eb0, const float* __restrict__ eb1,
    const float* __restrict__ db0, const float* __restrict__ db1,
    const float* __restrict__ projW, const float* __restrict__ projb,
    float* __restrict__ out)
{
  __shared__ __align__(16) uint2 sA[4 * 128 * 8];   // 32768 B
  __shared__ __align__(16) uint2 sB[4 * 64 * 8];    // 16384 B
  float* red = reinterpret_cast<float*>(sA);        // split-K overlay (post-drain)

  const int tid  = threadIdx.x;
  const int lane = tid & 31;
  const int wid  = tid >> 5;
  const int wk   = wid & 1;
  const int wm   = wid >> 1;
  const int gid  = lane >> 2;
  const int q    = lane & 3;
  const int bx   = blockIdx.x;
  const int grp  = bx >> 6;
  const int nBase = (bx & 63) * 64;

  // staging maps
  const int aRow = tid >> 1, half = tid & 1, half4 = half * 4;
  const int fA = (aRow & 2) * 3;
  const int bRow = tid >> 2, quad2 = (tid & 3) * 2;
  const int fB = (bRow & 2) * 3;
  const int colB = nBase + bRow;

  const uint32_t sAu = smem_u32(sA);
  const uint32_t sBu = smem_u32(sB);

  unsigned barNo = 0;
  auto grid_barrier = [&]() {
    ++barNo;
    __threadfence();
    __syncthreads();
    if (tid == 0) {
      unsigned old = atomicAdd(&g_bar_cnt, 1u);
      if (old == NCTA - 1) {
        g_bar_cnt = 0;
        __threadfence();
        g_bar_epoch = barNo;
      } else {
        while (g_bar_epoch < barNo) __nanosleep(32);
      }
    }
    __syncthreads();
    __threadfence();
  };

  auto step = [&](const uint2* __restrict__ Apx, int pxStride, int pxPairs,
                  const uint2* __restrict__ Ahp,
                  const uint2* __restrict__ gW, int P,
                  const float* __restrict__ bias, float* __restrict__ cS,
                  uint2* __restrict__ hOutP, int predMode, float predVal) {
    const int S = P >> 4;                     // supers (2 chunks each)
    const size_t bWoff = (size_t)colB * P;

    auto ISSUE = [&](int si, int st, bool skipA) {
#pragma unroll
      for (int u = 0; u < 2; ++u) {
        const int kb = si * 2 + u;
        if (!skipA) {
#pragma unroll
          for (int i = 0; i < 2; ++i) {
            const int p = half4 + i * 2;
            const int gp = kb * 8 + p;
            const uint2* src = (gp < pxPairs)
                ? (Apx + (size_t)aRow * pxStride + gp)
                : (Ahp + (size_t)aRow * HP + (gp - pxPairs));
            const uint32_t dst = sAu + (((st * 2 + u) * 128 + aRow) * 8 + (p ^ fA)) * 8;
            CP_ASYNC16(dst, src);
          }
        }
        {
          const int gp = kb * 8 + quad2;
          const uint2* src = gW + bWoff + gp;
          const uint32_t dst = sBu + (((st * 2 + u) * 64 + bRow) * 8 + (quad2 ^ fB)) * 8;
          CP_ASYNC16(dst, src);
        }
      }
    };

    float acc[2][8][4];
#pragma unroll
    for (int a = 0; a < 2; ++a)
#pragma unroll
      for (int b = 0; b < 8; ++b)
#pragma unroll
        for (int c = 0; c < 4; ++c) acc[a][b][c] = 0.f;

    // prologue
    ISSUE(0, 0, predMode != 0);
    CP_COMMIT();
    ISSUE(1, 1, false);
    CP_COMMIT();
    if (predMode) {
      // chunks 0,1 (slots 0,1): pair 0 = (pred, 0) split; rest zero
      const uint2 z2 = make_uint2(0u, 0u);
      const uint2 pv = split2(predVal, 0.f);
#pragma unroll
      for (int u = 0; u < 2; ++u) {
#pragma unroll
        for (int i = 0; i < 2; ++i) {
          const int p = half4 + i * 2;
          const int gp = u * 8 + p;
          uint2* d = &sA[(u * 128 + aRow) * 8 + (p ^ fA)];
          d[0] = (gp == 0) ? pv : z2;
          d[1] = z2;
        }
      }
    }
    CP_WAIT1();
    __syncthreads();

    for (int s = 0; s < S; ++s) {
      const int slot = (s & 1) * 2 + wk;
      const uint2* As = sA + slot * (128 * 8);
      const uint2* Bs = sB + slot * (64 * 8);
      uint32_t aH[2][4], aL[2][4];
#pragma unroll
      for (int mt = 0; mt < 2; ++mt) {
        const int r = wm * 32 + mt * 16 + gid;
        const int fr = (r & 2) * 3;
        const uint2 u0 = As[r * 8 + (q ^ fr)];
        const uint2 u1 = As[(r + 8) * 8 + (q ^ fr)];
        const uint2 u2 = As[r * 8 + ((q + 4) ^ fr)];
        const uint2 u3 = As[(r + 8) * 8 + ((q + 4) ^ fr)];
        aH[mt][0] = u0.x; aH[mt][1] = u1.x; aH[mt][2] = u2.x; aH[mt][3] = u3.x;
        aL[mt][0] = u0.y; aL[mt][1] = u1.y; aL[mt][2] = u2.y; aL[mt][3] = u3.y;
      }
#pragma unroll
      for (int nt = 0; nt < 8; ++nt) {
        const int n = nt * 8 + gid;
        const int fn = (n & 2) * 3;
        const uint2 v0 = Bs[n * 8 + (q ^ fn)];
        const uint2 v1 = Bs[n * 8 + ((q + 4) ^ fn)];
        const uint32_t bH[2] = {v0.x, v1.x};
        const uint32_t bL[2] = {v0.y, v1.y};
#pragma unroll
        for (int mt = 0; mt < 2; ++mt) {
          mma_bf16(acc[mt][nt], aL[mt], bH);
          mma_bf16(acc[mt][nt], aH[mt], bL);
          mma_bf16(acc[mt][nt], aH[mt], bH);
        }
      }
      __syncthreads();
      if (s + 2 < S) ISSUE(s + 2, s & 1, false);
      CP_COMMIT();
      CP_WAIT1();
      __syncthreads();
    }
    CP_WAIT0();
    __syncthreads();

    // ---- split-K reduction: wk==1 hands 64 accs to wk==0 partner ----
    float* af = &acc[0][0][0];
    const int slotr = (wm * 32 + lane) * 64;
    if (wk) {
#pragma unroll
      for (int i = 0; i < 64; ++i) red[slotr + i] = af[i];
    }
    __syncthreads();
    if (!wk) {
#pragma unroll
      for (int i = 0; i < 64; ++i) af[i] += red[slotr + i];

      // ---- epilogue: bias + activations + c update + paired-h store ----
#pragma unroll
      for (int mt = 0; mt < 2; ++mt) {
#pragma unroll
        for (int nt = 0; nt < 8; ++nt) {
          const float p0 = __shfl_xor_sync(0xffffffffu, acc[mt][nt][0], 1);
          const float p1 = __shfl_xor_sync(0xffffffffu, acc[mt][nt][1], 1);
          const float p2 = __shfl_xor_sync(0xffffffffu, acc[mt][nt][2], 1);
          const float p3 = __shfl_xor_sync(0xffffffffu, acc[mt][nt][3], 1);
          const int cg = nBase + nt * 8 + 2 * q;
          const int j  = cg >> 2;               // odd lanes compute unused values
          const float bi = bias[j];
          const float bf = bias[HID + j];
          const float bg = bias[2 * HID + j];
          const float bo = bias[3 * HID + j];
          const int r0 = wm * 32 + mt * 16 + gid;
          const int r1 = r0 + 8;
          float hn0, hn1;
          {
            const float ig = sigmoidf_(acc[mt][nt][0] + bi);
            const float fg = sigmoidf_(acc[mt][nt][1] + bf);
            const float gg = tanhf(p0 + bg);
            const float og = sigmoidf_(p1 + bo);
            const float cn = fg * cS[r0 * HID + j] + ig * gg;
            if ((lane & 1) == 0) cS[r0 * HID + j] = cn;
            hn0 = og * tanhf(cn);
          }
          {
            const float ig = sigmoidf_(acc[mt][nt][2] + bi);
            const float fg = sigmoidf_(acc[mt][nt][3] + bf);
            const float gg = tanhf(p2 + bg);
            const float og = sigmoidf_(p3 + bo);
            const float cn = fg * cS[r1 * HID + j] + ig * gg;
            if ((lane & 1) == 0) cS[r1 * HID + j] = cn;
            hn1 = og * tanhf(cn);
          }
          const float x0 = __shfl_xor_sync(0xffffffffu, hn0, 2);
          const float x1 = __shfl_xor_sync(0xffffffffu, hn1, 2);
          if (q == 0) {
            const int jp = (nBase + nt * 8) >> 3;
            hOutP[(size_t)r0 * HP + jp] = split2(hn0, x0);
            hOutP[(size_t)r1 * HP + jp] = split2(hn1, x1);
          }
        }
      }
    }
  };

  // proj: this thread computes pred for batch row aRow (paired with tid^1)
  auto projPred = [&](const uint2* __restrict__ h1base) -> float {
    const uint2* hr = h1base + (size_t)aRow * HP;
    float s = 0.f;
    for (int p = half; p < HP; p += 2) {
      const uint2 u = hr[p];
      const float v0 = __uint_as_float(u.x << 16) + __uint_as_float(u.y << 16);
      const float v1 = __uint_as_float(u.x & 0xFFFF0000u) +
                       __uint_as_float(u.y & 0xFFFF0000u);
      s += v0 * projW[2 * p] + v1 * projW[2 * p + 1];
    }
    s += __shfl_xor_sync(0xffffffffu, s, 1);
    return s + projb[0];
  };

  const size_t HS = (size_t)NB * HP;

  // -------- encoder wavefront: round r = enc0 t=r  ||  enc1 t=r-1 --------
  for (int r = 0; r <= TSTEPS; ++r) {
    if (grp == 0 && r < TSTEPS) {
      const uint2* ah = r ? (g_ys0p + (size_t)(r - 1) * HS) : g_zerop;
      step(g_xp + (size_t)r * NB * XP, XP, XP, ah, g_We0, P0, eb0, g_c0,
           g_ys0p + (size_t)r * HS, 0, 0.f);
    }
    if (grp == 1 && r >= 1) {
      const int t = r - 1, cur = t & 1, prv = (t - 1) & 1;
      const uint2* ah = t ? (g_hBp + (size_t)prv * HS) : g_zerop;
      step(g_ys0p + (size_t)t * HS, HP, HP, ah, g_We1, P1, eb1, g_c1,
           g_hBp + (size_t)cur * HS, 0, 0.f);
    }
    grid_barrier();
  }
  // -------- decoder: 2 rounds per t, proj folded into dec0 round --------
  for (int t = 0; t < HORIZON; ++t) {
    const int cur = t & 1, prv = (t - 1) & 1;
    if (grp == 0) {
      const uint2* ah0 = t ? (g_hd0p + (size_t)prv * HS)
                           : (g_ys0p + (size_t)(TSTEPS - 1) * HS);
      if (t == 0) {
        step(g_predp, XP, XP, ah0, g_Wd0, P0, db0, g_c0,
             g_hd0p + (size_t)cur * HS, 0, 0.f);
      } else {
        const float pv = projPred(g_hd1p + (size_t)prv * HS);
        if (bx == 0 && half == 0) out[aRow * HORIZON + (t - 1)] = pv;
        step(g_predp, XP, XP, ah0, g_Wd0, P0, db0, g_c0,
             g_hd0p + (size_t)cur * HS, 1, pv);
      }
    }
    grid_barrier();
    if (grp == 1) {
      const uint2* ah1 = t ? (g_hd1p + (size_t)prv * HS) : (g_hBp + HS);
      step(g_hd0p + (size_t)cur * HS, HP, HP, ah1, g_Wd1, P1, db1, g_c1,
           g_hd1p + (size_t)cur * HS, 0, 0.f);
    }
    grid_barrier();
  }
  // final prediction (out column HORIZON-1)
  if (bx == 0) {
    const float pv = projPred(g_hd1p + (size_t)((HORIZON - 1) & 1) * HS);
    if (half == 0) out[aRow * HORIZON + (HORIZON - 1)] = pv;
  }
}

// ---------------- init: weight split/interleave + staging + zeros ----------------
__global__ void init_kernel(
    const float* __restrict__ x,
    const float* __restrict__ eWih0, const float* __restrict__ eWhh0,
    const float* __restrict__ eWih1, const float* __restrict__ eWhh1,
    const float* __restrict__ dWih0, const float* __restrict__ dWhh0,
    const float* __restrict__ dWih1, const float* __restrict__ dWhh1)
{
  const int nthreads = gridDim.x * blockDim.x;
  const int tid0 = blockIdx.x * blockDim.x + threadIdx.x;
  if (tid0 == 0) { g_bar_cnt = 0; g_bar_epoch = 0; }

  for (size_t i = tid0; i < (size_t)4096 * P0; i += nthreads) {
    const int c = (int)(i / P0);
    const int p = (int)(i % P0);
    const int orow = (c & 3) * HID + (c >> 2);
    const int k = 2 * p;
    float e0a, e0b, d0a, d0b;
    if (k < 32) {
      e0a = (k < 8) ? eWih0[orow * 8 + k] : 0.f;
      e0b = (k + 1 < 8) ? eWih0[orow * 8 + k + 1] : 0.f;
      d0a = (k == 0) ? dWih0[orow] : 0.f;
      d0b = 0.f;
    } else {
      e0a = eWhh0[(size_t)orow * HID + (k - 32)];
      e0b = eWhh0[(size_t)orow * HID + (k - 31)];
      d0a = dWhh0[(size_t)orow * HID + (k - 32)];
      d0b = dWhh0[(size_t)orow * HID + (k - 31)];
    }
    g_We0[i] = split2(e0a, e0b);
    g_Wd0[i] = split2(d0a, d0b);
  }
  for (size_t i = tid0; i < (size_t)4096 * P1; i += nthreads) {
    const int c = (int)(i / P1);
    const int p = (int)(i % P1);
    const int orow = (c & 3) * HID + (c >> 2);
    const int k = 2 * p;
    float e1a, e1b, d1a, d1b;
    if (k < HID) {
      e1a = eWih1[(size_t)orow * HID + k];
      e1b = eWih1[(size_t)orow * HID + k + 1];
      d1a = dWih1[(size_t)orow * HID + k];
      d1b = dWih1[(size_t)orow * HID + k + 1];
    } else {
      e1a = eWhh1[(size_t)orow * HID + (k - HID)];
      e1b = eWhh1[(size_t)orow * HID + (k - HID + 1)];
      d1a = dWhh1[(size_t)orow * HID + (k - HID)];
      d1b = dWhh1[(size_t)orow * HID + (k - HID + 1)];
    }
    g_We1[i] = split2(e1a, e1b);
    g_Wd1[i] = split2(d1a, d1b);
  }
  for (size_t i = tid0; i < (size_t)TSTEPS * NB * XP; i += nthreads) {
    const int p = (int)(i & (XP - 1));
    const int m = (int)((i >> 4) & (NB - 1));
    const int t = (int)(i >> 11);
    const int k = 2 * p;
    const float v0 = (k < 8) ? x[((size_t)m * TSTEPS + t) * 8 + k] : 0.f;
    const float v1 = (k + 1 < 8) ? x[((size_t)m * TSTEPS + t) * 8 + k + 1] : 0.f;
    g_xp[i] = split2(v0, v1);
  }
  for (int i = tid0; i < NB * XP; i += nthreads) {
    const int m = i >> 4;
    const int p = i & (XP - 1);
    g_predp[i] = (p == 0)
        ? split2(x[((size_t)m * TSTEPS + (TSTEPS - 1)) * 8], 0.f)
        : make_uint2(0u, 0u);
  }
  for (int i = tid0; i < NB * HP; i += nthreads) g_zerop[i] = make_uint2(0u, 0u);
  for (int i = tid0; i < NB * HID; i += nthreads) { g_c0[i] = 0.f; g_c1[i] = 0.f; }
}

// ---------------- host side ------------------------------------------------------
extern "C" void kernel_launch(void* const* d_in, const int* in_sizes, int n_in,
                              void* d_out, int out_size) {
  const float* x     = (const float*)d_in[0];
  const float* eWih0 = (const float*)d_in[1];
  const float* eWhh0 = (const float*)d_in[2];
  const float* eb0   = (const float*)d_in[3];
  const float* eWih1 = (const float*)d_in[4];
  const float* eWhh1 = (const float*)d_in[5];
  const float* eb1   = (const float*)d_in[6];
  const float* dWih0 = (const float*)d_in[7];
  const float* dWhh0 = (const float*)d_in[8];
  const float* db0   = (const float*)d_in[9];
  const float* dWih1 = (const float*)d_in[10];
  const float* dWhh1 = (const float*)d_in[11];
  const float* db1   = (const float*)d_in[12];
  const float* projW = (const float*)d_in[13];
  const float* projb = (const float*)d_in[14];
  float* out = (float*)d_out;

  init_kernel<<<4096, 512>>>(x, eWih0, eWhh0, eWih1, eWhh1,
                             dWih0, dWhh0, dWih1, dWhh1);
  lstm_persist<<<NCTA, NTHR>>>(eb0, eb1, db0, db1, projW, projb, out);
}

// round 11
// speedup vs baseline: 1.3034x; 1.3034x over previous
#include <cuda_runtime.h>
#include <cuda_bf16.h>
#include <cstdint>
#include <cstddef>

#define HID 1024
#define NB 128
#define TSTEPS 256
#define HORIZON 24
#define NCTA 128
#define NTHR 256
#define HP 512                 // bf16x2 (hi,lo) pairs per 1024-wide row
#define XP 16                  // pairs in x/pred block (32 k, zero padded)
#define P0 (XP + HP)           // 528 pairs  : enc0/dec0 K
#define P1 (2 * HP)            // 1024 pairs : enc1/dec1 K

// ---------------- persistent scratch (__device__ globals; no allocs) -------------
// weights: [interleaved_col (4j+g)][pair] as uint2(hi bf16x2, lo bf16x2)
__device__ __align__(16) uint2 g_We0[(size_t)4096 * P0];
__device__ __align__(16) uint2 g_We1[(size_t)4096 * P1];
__device__ __align__(16) uint2 g_Wd0[(size_t)4096 * P0];
__device__ __align__(16) uint2 g_Wd1[(size_t)4096 * P1];
// activations as split pairs
__device__ __align__(16) uint2 g_ys0p[(size_t)TSTEPS * NB * HP];
__device__ __align__(16) uint2 g_hBp[2 * NB * HP];
__device__ __align__(16) uint2 g_hd0p[2 * NB * HP];
__device__ __align__(16) uint2 g_hd1p[2 * NB * HP];
__device__ __align__(16) uint2 g_zerop[NB * HP];
__device__ __align__(16) uint2 g_xp[(size_t)TSTEPS * NB * XP];
__device__ __align__(16) uint2 g_predp[NB * XP];
__device__ float g_c0[NB * HID];
__device__ float g_c1[NB * HID];
__device__ unsigned g_bar_cnt;
__device__ volatile unsigned g_bar_epoch;

// ---------------- helpers --------------------------------------------------------
__device__ __forceinline__ uint32_t bf2pack(float hi, float lo) {
  uint32_t r;
  asm("cvt.rn.bf16x2.f32 %0, %1, %2;" : "=r"(r) : "f"(hi), "f"(lo));
  return r;
}
__device__ __forceinline__ uint2 split2(float v0, float v1) {
  uint32_t hp = bf2pack(v1, v0);
  float h0 = __uint_as_float(hp << 16);
  float h1 = __uint_as_float(hp & 0xFFFF0000u);
  uint32_t lp = bf2pack(v1 - h1, v0 - h0);
  return make_uint2(hp, lp);
}
__device__ __forceinline__ void mma_bf16(float d[4], const uint32_t a[4], const uint32_t b[2]) {
  asm volatile(
      "mma.sync.aligned.m16n8k16.row.col.f32.bf16.bf16.f32 "
      "{%0,%1,%2,%3}, {%4,%5,%6,%7}, {%8,%9}, {%0,%1,%2,%3};\n"
      : "+f"(d[0]), "+f"(d[1]), "+f"(d[2]), "+f"(d[3])
      : "r"(a[0]), "r"(a[1]), "r"(a[2]), "r"(a[3]), "r"(b[0]), "r"(b[1]));
}
__device__ __forceinline__ float sigmoidf_(float x) { return 1.f / (1.f + expf(-x)); }

__device__ __forceinline__ uint32_t smem_u32(const void* p) {
  uint32_t a;
  asm("{ .reg .u64 t; cvta.to.shared.u64 t, %1; cvt.u32.u64 %0, t; }" : "=r"(a) : "l"(p));
  return a;
}
#define CP_ASYNC16(dst, src) \
  asm volatile("cp.async.cg.shared.global [%0], [%1], 16;" :: "r"(dst), "l"(src) : "memory")
#define CP_COMMIT() asm volatile("cp.async.commit_group;" ::: "memory")
#define CP_WAIT1()  asm volatile("cp.async.wait_group 1;" ::: "memory")
#define CP_WAIT0()  asm volatile("cp.async.wait_group 0;" ::: "memory")

// ---------------- persistent kernel ----------------------------------------------
// 128 CTAs: mBase=(bx>>6)*64, nBase=(bx&63)*64. 8 warps: wk=wid&1 (K half),
// wn=(wid>>1)&1, wm=wid>>2 -> warp tile 32x32, acc 32 regs.
// Super = 2 chunks of K=16 (8 pairs each). 2 stages x 2 chunks = 4 smem slots.
// XOR swizzle f(r)=(r&2)*2, stride 8 uint2/row -> conflict-free. 32KB static smem.
// cp.async discipline identical to R8 (proven in-container): commit each iter,
// wait_group 1 at loop bottom.
__global__ void __launch_bounds__(NTHR, 1) lstm_persist(
    const float* __restrict__ eb0, const float* __restrict__ eb1,
    const float* __restrict__ db0, const float* __restrict__ db1,
    const float* __restrict__ projW, const float* __restrict__ projb,
    float* __restrict__ out)
{
  __shared__ __align__(16) uint2 sA[4 * 64 * 8];    // 16384 B
  __shared__ __align__(16) uint2 sB[4 * 64 * 8];    // 16384 B
  float* red = reinterpret_cast<float*>(sA);        // overlay (post-drain only)

  const int tid  = threadIdx.x;
  const int lane = tid & 31;
  const int wid  = tid >> 5;
  const int wk   = wid & 1;
  const int wn   = (wid >> 1) & 1;
  const int wm   = wid >> 2;
  const int gid  = lane >> 2;
  const int q    = lane & 3;
  const int bx   = blockIdx.x;
  const int mBase = (bx >> 6) * 64;
  const int nBase = (bx & 63) * 64;

  // staging map: thread -> row (0..63), 16B quad (2 pairs)
  const int aRow  = tid >> 2;
  const int quad2 = (tid & 3) * 2;
  const int fS    = (aRow & 2) * 2;
  const int mG    = mBase + aRow;
  const int colB  = nBase + aRow;

  const uint32_t sAu = smem_u32(sA);
  const uint32_t sBu = smem_u32(sB);

  unsigned barNo = 0;
  auto grid_barrier = [&]() {
    ++barNo;
    __threadfence();
    __syncthreads();
    if (tid == 0) {
      unsigned old = atomicAdd(&g_bar_cnt, 1u);
      if (old == NCTA - 1) {
        g_bar_cnt = 0;
        __threadfence();
        g_bar_epoch = barNo;
      } else {
        while (g_bar_epoch < barNo) __nanosleep(32);
      }
    }
    __syncthreads();
    __threadfence();
  };

  auto step = [&](const uint2* __restrict__ Apx, int pxStride, int pxPairs,
                  const uint2* __restrict__ Ahp,
                  const uint2* __restrict__ gW, int P,
                  const float* __restrict__ bias, float* __restrict__ cS,
                  uint2* __restrict__ hOutP) {
    const int S = P >> 4;                      // supers of 2 chunks
    const size_t bWoff = (size_t)colB * P;

    auto ISSUE = [&](int si, int st) {
#pragma unroll
      for (int u = 0; u < 2; ++u) {
        const int kb = si * 2 + u;
        const int gp = kb * 8 + quad2;
        const uint2* asrc = (gp < pxPairs)
            ? (Apx + (size_t)mG * pxStride + gp)
            : (Ahp + (size_t)mG * HP + (gp - pxPairs));
        const uint32_t dA = sAu + (((st * 2 + u) * 64 + aRow) * 8 + (quad2 ^ fS)) * 8;
        CP_ASYNC16(dA, asrc);
        const uint32_t dB = sBu + (((st * 2 + u) * 64 + aRow) * 8 + (quad2 ^ fS)) * 8;
        CP_ASYNC16(dB, gW + bWoff + gp);
      }
    };

    float acc[2][4][4];
#pragma unroll
    for (int a = 0; a < 2; ++a)
#pragma unroll
      for (int b = 0; b < 4; ++b)
#pragma unroll
        for (int c = 0; c < 4; ++c) acc[a][b][c] = 0.f;

    ISSUE(0, 0); CP_COMMIT();
    ISSUE(1, 1); CP_COMMIT();
    CP_WAIT1();                        // stage 0 (group 0) complete
    __syncthreads();

    for (int s = 0; s < S; ++s) {
      const int st = s & 1;
      const uint2* As = sA + (st * 2 + wk) * 512;
      const uint2* Bs = sB + (st * 2 + wk) * 512;
      uint32_t aH[2][4], aL[2][4], bH[4][2], bL[4][2];
#pragma unroll
      for (int mt = 0; mt < 2; ++mt) {
        const int r = wm * 32 + mt * 16 + gid;
        const int fr = (r & 2) * 2;
        const uint2 u0 = As[r * 8 + (q ^ fr)];
        const uint2 u1 = As[(r + 8) * 8 + (q ^ fr)];
        const uint2 u2 = As[r * 8 + ((q + 4) ^ fr)];
        const uint2 u3 = As[(r + 8) * 8 + ((q + 4) ^ fr)];
        aH[mt][0] = u0.x; aH[mt][1] = u1.x; aH[mt][2] = u2.x; aH[mt][3] = u3.x;
        aL[mt][0] = u0.y; aL[mt][1] = u1.y; aL[mt][2] = u2.y; aL[mt][3] = u3.y;
      }
#pragma unroll
      for (int nt = 0; nt < 4; ++nt) {
        const int n = wn * 32 + nt * 8 + gid;
        const int fn = (n & 2) * 2;
        const uint2 v0 = Bs[n * 8 + (q ^ fn)];
        const uint2 v1 = Bs[n * 8 + ((q + 4) ^ fn)];
        bH[nt][0] = v0.x; bH[nt][1] = v1.x;
        bL[nt][0] = v0.y; bL[nt][1] = v1.y;
      }
      __syncthreads();                 // all reads of stage st done
      if (s + 2 < S) ISSUE(s + 2, st); // refill this stage for super s+2
      CP_COMMIT();
#pragma unroll
      for (int mt = 0; mt < 2; ++mt)
#pragma unroll
        for (int nt = 0; nt < 4; ++nt) {
          mma_bf16(acc[mt][nt], aL[mt], bH[nt]);
          mma_bf16(acc[mt][nt], aH[mt], bL[nt]);
          mma_bf16(acc[mt][nt], aH[mt], bH[nt]);
        }
      CP_WAIT1();                      // next stage's group complete
      __syncthreads();
    }
    CP_WAIT0();
    __syncthreads();

    // ---- split-K reduction: wk==1 hands accs to wk==0 partner ----
    float* af = &acc[0][0][0];
    const int slotr = (((wid >> 1) * 32) + lane) * 32;
    if (wk) {
#pragma unroll
      for (int i = 0; i < 32; ++i) red[slotr + i] = af[i];
    }
    __syncthreads();
    if (!wk) {
#pragma unroll
      for (int i = 0; i < 32; ++i) af[i] += red[slotr + i];

      // ---- epilogue: bias + activations + c update + paired-h store ----
      const int cWarp = nBase + wn * 32;
      const int mWarp = mBase + wm * 32;
#pragma unroll
      for (int mt = 0; mt < 2; ++mt) {
#pragma unroll
        for (int nt = 0; nt < 4; ++nt) {
          const float p0 = __shfl_xor_sync(0xffffffffu, acc[mt][nt][0], 1);
          const float p1 = __shfl_xor_sync(0xffffffffu, acc[mt][nt][1], 1);
          const float p2 = __shfl_xor_sync(0xffffffffu, acc[mt][nt][2], 1);
          const float p3 = __shfl_xor_sync(0xffffffffu, acc[mt][nt][3], 1);
          const int cg = cWarp + nt * 8 + 2 * q;
          const int j  = cg >> 2;                 // odd lanes: unused values
          const float bi = bias[j];
          const float bf = bias[HID + j];
          const float bg = bias[2 * HID + j];
          const float bo = bias[3 * HID + j];
          const int r0 = mWarp + mt * 16 + gid;
          const int r1 = r0 + 8;
          float hn0, hn1;
          {
            const float ig = sigmoidf_(acc[mt][nt][0] + bi);
            const float fg = sigmoidf_(acc[mt][nt][1] + bf);
            const float gg = tanhf(p0 + bg);
            const float og = sigmoidf_(p1 + bo);
            const float cn = fg * cS[r0 * HID + j] + ig * gg;
            if ((lane & 1) == 0) cS[r0 * HID + j] = cn;
            hn0 = og * tanhf(cn);
          }
          {
            const float ig = sigmoidf_(acc[mt][nt][2] + bi);
            const float fg = sigmoidf_(acc[mt][nt][3] + bf);
            const float gg = tanhf(p2 + bg);
            const float og = sigmoidf_(p3 + bo);
            const float cn = fg * cS[r1 * HID + j] + ig * gg;
            if ((lane & 1) == 0) cS[r1 * HID + j] = cn;
            hn1 = og * tanhf(cn);
          }
          const float x0 = __shfl_xor_sync(0xffffffffu, hn0, 2);
          const float x1 = __shfl_xor_sync(0xffffffffu, hn1, 2);
          if (q == 0) {
            const int jp = (cWarp + nt * 8) >> 3;
            hOutP[(size_t)r0 * HP + jp] = split2(hn0, x0);
            hOutP[(size_t)r1 * HP + jp] = split2(hn1, x1);
          }
        }
      }
    }
  };

  const size_t HS = (size_t)NB * HP;

  // -------- encoder layer 0 --------
  for (int t = 0; t < TSTEPS; ++t) {
    const uint2* ah = t ? (g_ys0p + (size_t)(t - 1) * HS) : g_zerop;
    step(g_xp + (size_t)t * NB * XP, XP, XP, ah, g_We0, P0, eb0, g_c0,
         g_ys0p + (size_t)t * HS);
    grid_barrier();
  }
  // -------- encoder layer 1 --------
  for (int t = 0; t < TSTEPS; ++t) {
    const int cur = t & 1, prv = (t - 1) & 1;
    const uint2* ah = t ? (g_hBp + (size_t)prv * HS) : g_zerop;
    step(g_ys0p + (size_t)t * HS, HP, HP, ah, g_We1, P1, eb1, g_c1,
         g_hBp + (size_t)cur * HS);
    grid_barrier();
  }
  // -------- decoder --------
  for (int t = 0; t < HORIZON; ++t) {
    const int cur = t & 1, prv = (t - 1) & 1;
    const uint2* ah0 = t ? (g_hd0p + (size_t)prv * HS)
                         : (g_ys0p + (size_t)(TSTEPS - 1) * HS);
    step(g_predp, XP, XP, ah0, g_Wd0, P0, db0, g_c0, g_hd0p + (size_t)cur * HS);
    grid_barrier();
    const uint2* ah1 = t ? (g_hd1p + (size_t)prv * HS) : (g_hBp + HS);
    step(g_hd0p + (size_t)cur * HS, HP, HP, ah1, g_Wd1, P1, db1, g_c1,
         g_hd1p + (size_t)cur * HS);
    grid_barrier();
    // projection: CTA bx handles batch row bx
    {
      const uint2* hr = g_hd1p + (size_t)cur * HS + (size_t)bx * HP;
      float s = 0.f;
      for (int p = tid; p < HP; p += NTHR) {
        const uint2 u = hr[p];
        const float v0 = __uint_as_float(u.x << 16) + __uint_as_float(u.y << 16);
        const float v1 = __uint_as_float(u.x & 0xFFFF0000u) +
                         __uint_as_float(u.y & 0xFFFF0000u);
        s += v0 * projW[2 * p] + v1 * projW[2 * p + 1];
      }
#pragma unroll
      for (int o = 16; o; o >>= 1) s += __shfl_xor_sync(0xffffffffu, s, o);
      if (lane == 0) red[wid] = s;
      __syncthreads();
      if (tid == 0) {
        float tot = 0.f;
#pragma unroll
        for (int i = 0; i < 8; ++i) tot += red[i];
        const float p = tot + projb[0];
        out[bx * HORIZON + t] = p;
        g_predp[bx * XP] = split2(p, 0.f);
      }
      __syncthreads();
    }
    grid_barrier();
  }
}

// ---------------- init: weight split/interleave + staging + zeros ----------------
__global__ void init_kernel(
    const float* __restrict__ x,
    const float* __restrict__ eWih0, const float* __restrict__ eWhh0,
    const float* __restrict__ eWih1, const float* __restrict__ eWhh1,
    const float* __restrict__ dWih0, const float* __restrict__ dWhh0,
    const float* __restrict__ dWih1, const float* __restrict__ dWhh1)
{
  const int nthreads = gridDim.x * blockDim.x;
  const int tid0 = blockIdx.x * blockDim.x + threadIdx.x;
  if (tid0 == 0) { g_bar_cnt = 0; g_bar_epoch = 0; }

  for (size_t i = tid0; i < (size_t)4096 * P0; i += nthreads) {
    const int c = (int)(i / P0);
    const int p = (int)(i % P0);
    const int orow = (c & 3) * HID + (c >> 2);
    const int k = 2 * p;
    float e0a, e0b, d0a, d0b;
    if (k < 32) {
      e0a = (k < 8) ? eWih0[orow * 8 + k] : 0.f;
      e0b = (k + 1 < 8) ? eWih0[orow * 8 + k + 1] : 0.f;
      d0a = (k == 0) ? dWih0[orow] : 0.f;
      d0b = 0.f;
    } else {
      e0a = eWhh0[(size_t)orow * HID + (k - 32)];
      e0b = eWhh0[(size_t)orow * HID + (k - 31)];
      d0a = dWhh0[(size_t)orow * HID + (k - 32)];
      d0b = dWhh0[(size_t)orow * HID + (k - 31)];
    }
    g_We0[i] = split2(e0a, e0b);
    g_Wd0[i] = split2(d0a, d0b);
  }
  for (size_t i = tid0; i < (size_t)4096 * P1; i += nthreads) {
    const int c = (int)(i / P1);
    const int p = (int)(i % P1);
    const int orow = (c & 3) * HID + (c >> 2);
    const int k = 2 * p;
    float e1a, e1b, d1a, d1b;
    if (k < HID) {
      e1a = eWih1[(size_t)orow * HID + k];
      e1b = eWih1[(size_t)orow * HID + k + 1];
      d1a = dWih1[(size_t)orow * HID + k];
      d1b = dWih1[(size_t)orow * HID + k + 1];
    } else {
      e1a = eWhh1[(size_t)orow * HID + (k - HID)];
      e1b = eWhh1[(size_t)orow * HID + (k - HID + 1)];
      d1a = dWhh1[(size_t)orow * HID + (k - HID)];
      d1b = dWhh1[(size_t)orow * HID + (k - HID + 1)];
    }
    g_We1[i] = split2(e1a, e1b);
    g_Wd1[i] = split2(d1a, d1b);
  }
  for (size_t i = tid0; i < (size_t)TSTEPS * NB * XP; i += nthreads) {
    const int p = (int)(i & (XP - 1));
    const int m = (int)((i >> 4) & (NB - 1));
    const int t = (int)(i >> 11);
    const int k = 2 * p;
    const float v0 = (k < 8) ? x[((size_t)m * TSTEPS + t) * 8 + k] : 0.f;
    const float v1 = (k + 1 < 8) ? x[((size_t)m * TSTEPS + t) * 8 + k + 1] : 0.f;
    g_xp[i] = split2(v0, v1);
  }
  for (int i = tid0; i < NB * XP; i += nthreads) {
    const int m = i >> 4;
    const int p = i & (XP - 1);
    g_predp[i] = (p == 0)
        ? split2(x[((size_t)m * TSTEPS + (TSTEPS - 1)) * 8], 0.f)
        : make_uint2(0u, 0u);
  }
  for (int i = tid0; i < NB * HP; i += nthreads) g_zerop[i] = make_uint2(0u, 0u);
  for (int i = tid0; i < NB * HID; i += nthreads) { g_c0[i] = 0.f; g_c1[i] = 0.f; }
}

// ---------------- host side ------------------------------------------------------
extern "C" void kernel_launch(void* const* d_in, const int* in_sizes, int n_in,
                              void* d_out, int out_size) {
  const float* x     = (const float*)d_in[0];
  const float* eWih0 = (const float*)d_in[1];
  const float* eWhh0 = (const float*)d_in[2];
  const float* eb0   = (const float*)d_in[3];
  const float* eWih1 = (const float*)d_in[4];
  const float* eWhh1 = (const float*)d_in[5];
  const float* eb1   = (const float*)d_in[6];
  const float* dWih0 = (const float*)d_in[7];
  const float* dWhh0 = (const float*)d_in[8];
  const float* db0   = (const float*)d_in[9];
  const float* dWih1 = (const float*)d_in[10];
  const float* dWhh1 = (const float*)d_in[11];
  const float* db1   = (const float*)d_in[12];
  const float* projW = (const float*)d_in[13];
  const float* projb = (const float*)d_in[14];
  float* out = (float*)d_out;

  init_kernel<<<4096, 512>>>(x, eWih0, eWhh0, eWih1, eWhh1,
                             dWih0, dWhh0, dWih1, dWhh1);
  lstm_persist<<<NCTA, NTHR>>>(eb0, eb1, db0, db1, projW, projb, out);
}